// round 12
// baseline (speedup 1.0000x reference)
#include <cuda_runtime.h>

#define NB 2
#define NN 8192
#define NP (NB*NN)      // 16384 points total
#define KK 16
#define PAD 68          // row stride (floats) for attn stage buffers
#define PTS 6           // points per attn block
#define PRS (PTS*16)    // 96 pairs per attn block
#define CAPA 24         // knn append-buffer capacity per lane

// ---------------- scratch (device globals; no allocation allowed) ----------------
__device__ float g_Wall[64*192];      // folded [i][c]: c 0-63 -> q, 64-127 -> k, 128-191 -> v
__device__ float g_call[192];         // folded biases
__device__ float g_X[NP*192];         // per-point q|k|v, row stride 192
__device__ float g_A[NP*64];          // per-point xyzp @ Wp1 (no bias)
__device__ int   g_idx[NP*KK];        // global neighbor row indices
__device__ float4 g_pts[NP];          // (x, y, z, |xyz|^2)

__device__ __forceinline__ float finf() { return __int_as_float(0x7f800000); }

// ================= fold: Mq=Wk@Wq etc, cq=bk@Wq etc =================
__global__ void fold_kernel(const float* __restrict__ Wk, const float* __restrict__ bk,
                            const float* __restrict__ Wq, const float* __restrict__ Wks,
                            const float* __restrict__ Wv) {
    int e = blockIdx.x * 256 + threadIdx.x;   // grid 16 x 256 = 4096
    int i = e >> 6, h = e & 63;
    float sq = 0.f, sk = 0.f, sv = 0.f;
    #pragma unroll 4
    for (int k = 0; k < 64; k++) {
        float wk = Wk[i*64 + k];
        sq = fmaf(wk, Wq [k*64 + h], sq);
        sk = fmaf(wk, Wks[k*64 + h], sk);
        sv = fmaf(wk, Wv [k*64 + h], sv);
    }
    g_Wall[i*192 + h]        = sq;
    g_Wall[i*192 + 64 + h]   = sk;
    g_Wall[i*192 + 128 + h]  = sv;
    if (blockIdx.x == 0 && threadIdx.x < 192) {
        int sec = threadIdx.x >> 6, hh = threadIdx.x & 63;
        const float* W = (sec == 0) ? Wq : ((sec == 1) ? Wks : Wv);
        float s = 0.f;
        #pragma unroll 4
        for (int k = 0; k < 64; k++) s = fmaf(bk[k], W[k*64 + hh], s);
        g_call[threadIdx.x] = s;
    }
}

// ================= transform: g_X = F @ Wall + call ; g_A = xyzp @ Wp1 ; g_pts =================
struct SmemT {
    float feat[16*65];
    float W[64*192];
    float c[192];
    float Wp1[4*64];
};

__global__ __launch_bounds__(192) void transform_kernel(
    const float* __restrict__ features, const float* __restrict__ xyzp,
    const float* __restrict__ Wp1) {
    extern __shared__ char smem_raw[];
    SmemT* sm = (SmemT*)smem_raw;
    int tid = threadIdx.x;            // 192 threads
    int base = blockIdx.x * 16;       // 16 rows per block

    for (int i4 = tid; i4 < 64*192/4; i4 += 192)
        ((float4*)sm->W)[i4] = ((const float4*)g_Wall)[i4];
    if (tid < 192) sm->c[tid] = g_call[tid];
    if (tid < 64)  ((float4*)sm->Wp1)[tid] = ((const float4*)Wp1)[tid];
    for (int i4 = tid; i4 < 16*64/4; i4 += 192) {
        int r = i4 >> 4, cc = i4 & 15;
        float4 v = ((const float4*)(features + (size_t)(base + r)*64))[cc];
        float* d = sm->feat + r*65 + cc*4;
        d[0] = v.x; d[1] = v.y; d[2] = v.z; d[3] = v.w;
    }
    if (tid < 16) {
        float4 p = ((const float4*)xyzp)[base + tid];
        float s = fmaf(p.x, p.x, fmaf(p.y, p.y, p.z*p.z));
        g_pts[base + tid] = make_float4(p.x, p.y, p.z, s);
    }
    __syncthreads();

    int rg = tid / 24;
    int cg = tid % 24;
    float acc[2][8];
    #pragma unroll
    for (int r = 0; r < 2; r++)
        #pragma unroll
        for (int c = 0; c < 8; c++) acc[r][c] = 0.f;

    #pragma unroll 4
    for (int i = 0; i < 64; i++) {
        float x0 = sm->feat[(rg*2    )*65 + i];
        float x1 = sm->feat[(rg*2 + 1)*65 + i];
        float4 w0 = *(const float4*)(sm->W + i*192 + cg*8);
        float4 w1 = *(const float4*)(sm->W + i*192 + cg*8 + 4);
        float wv[8] = {w0.x, w0.y, w0.z, w0.w, w1.x, w1.y, w1.z, w1.w};
        #pragma unroll
        for (int c = 0; c < 8; c++) {
            acc[0][c] = fmaf(x0, wv[c], acc[0][c]);
            acc[1][c] = fmaf(x1, wv[c], acc[1][c]);
        }
    }
    #pragma unroll
    for (int r = 0; r < 2; r++) {
        int row = base + rg*2 + r;
        float4 o0, o1;
        o0.x = acc[r][0] + sm->c[cg*8 + 0];
        o0.y = acc[r][1] + sm->c[cg*8 + 1];
        o0.z = acc[r][2] + sm->c[cg*8 + 2];
        o0.w = acc[r][3] + sm->c[cg*8 + 3];
        o1.x = acc[r][4] + sm->c[cg*8 + 4];
        o1.y = acc[r][5] + sm->c[cg*8 + 5];
        o1.z = acc[r][6] + sm->c[cg*8 + 6];
        o1.w = acc[r][7] + sm->c[cg*8 + 7];
        *(float4*)(g_X + (size_t)row*192 + cg*8)     = o0;
        *(float4*)(g_X + (size_t)row*192 + cg*8 + 4) = o1;
    }

    for (int o = tid; o < 16*64; o += 192) {
        int r = o >> 6, h = o & 63;
        const float* xp = xyzp + (size_t)(base + r)*4;
        float a = xp[0] * sm->Wp1[0*64 + h];
        a = fmaf(xp[1], sm->Wp1[1*64 + h], a);
        a = fmaf(xp[2], sm->Wp1[2*64 + h], a);
        a = fmaf(xp[3], sm->Wp1[3*64 + h], a);
        g_A[(size_t)(base + r)*64 + h] = a;
    }
}

// ================= knn: 8 lanes/query, prefetch batch, branchless append buffer =========
__device__ __forceinline__ void knn_merge16(float bk[16], int bi[16], float f, int ix) {
    bool t = f < bk[0];
    bk[0] = t ? f : bk[0];
    bi[0] = t ? ix : bi[0];
    #pragma unroll
    for (int s = 0; s < 15; s++) {
        bool csw = bk[s] < bk[s+1];
        float hi = fmaxf(bk[s], bk[s+1]);
        float lo = fminf(bk[s], bk[s+1]);
        int ih = csw ? bi[s+1] : bi[s];
        int il = csw ? bi[s]   : bi[s+1];
        bk[s] = hi; bk[s+1] = lo;
        bi[s] = ih; bi[s+1] = il;
    }
}

__global__ __launch_bounds__(128) void knn_kernel() {
    __shared__ unsigned long long sB[CAPA*128];   // per-lane buffer, entry e at [e*128+tid]
    int tid  = threadIdx.x;                       // 128: 16 queries x 8 lanes
    int b    = blockIdx.x >> 9;                   // 512 blocks per batch (grid 1024)
    int qloc = tid >> 3, sub = tid & 7;
    int n    = ((blockIdx.x & 511) << 4) + qloc;
    int row  = b*NN + n;
    float4 me = __ldg(&g_pts[row]);
    float xn = me.x, yn = me.y, zn = me.z;
    const float4* src = g_pts + (size_t)b*NN + (sub << 10);  // lane's 1024 range
    int jg0 = sub << 10;

    float bk[16];
    int   bi[16];
    #pragma unroll
    for (int s = 0; s < 16; s++) { bk[s] = finf(); bi[s] = 0; }
    float tau = finf();
    int cnt = 0;

    for (int ch = 0; ch < 128; ch++) {
        float4 cc[8];
        #pragma unroll
        for (int u = 0; u < 8; u++)
            cc[u] = __ldg(src + (ch << 3) + u);     // MLP=8 prefetch batch
        #pragma unroll
        for (int u = 0; u < 8; u++) {
            float f = fmaf(-2.f, fmaf(xn, cc[u].x, fmaf(yn, cc[u].y, zn*cc[u].z)), cc[u].w);
            ((float2*)sB)[cnt*128 + tid] = make_float2(f, __int_as_float(jg0 + (ch << 3) + u));
            cnt += (f <= tau) ? 1 : 0;
        }
        if (__ballot_sync(0xffffffffu, cnt > 16)) {
            for (int e = 0; e < cnt; e++) {
                float2 en = ((float2*)sB)[e*128 + tid];
                knn_merge16(bk, bi, en.x, __float_as_int(en.y));
            }
            cnt = 0;
            float t0 = fminf(bk[0], __shfl_xor_sync(0xffffffffu, bk[0], 1));
            t0 = fminf(t0, __shfl_xor_sync(0xffffffffu, t0, 2));
            tau = fminf(t0, __shfl_xor_sync(0xffffffffu, t0, 4));
        }
    }
    // final compaction (uniform)
    for (int e = 0; e < cnt; e++) {
        float2 en = ((float2*)sB)[e*128 + tid];
        knn_merge16(bk, bi, en.x, __float_as_int(en.y));
    }

    // pack final 16 as sortable u64 and publish for merge
    unsigned long long mine[16];
    #pragma unroll
    for (int s = 0; s < 16; s++) {
        unsigned u = __float_as_uint(bk[s]);
        u ^= ((unsigned)((int)u >> 31)) | 0x80000000u;
        mine[s] = ((unsigned long long)u << 13) | (unsigned)bi[s];
        sB[s*128 + tid] = mine[s];
    }
    __syncwarp();

    // exact rank of my 16 among the query's 128 (distinct: disjoint idx ranges)
    int rk[16];
    #pragma unroll
    for (int s = 0; s < 16; s++) rk[s] = 0;
    int lbase = tid & ~7;
    #pragma unroll 4
    for (int o = 0; o < 128; o++) {
        unsigned long long ov = sB[(o >> 3)*128 + lbase + (o & 7)];
        #pragma unroll
        for (int e = 0; e < 16; e++) rk[e] += (ov < mine[e]) ? 1 : 0;
    }
    #pragma unroll
    for (int e = 0; e < 16; e++)
        if (rk[e] < 16)
            g_idx[(size_t)row*16 + rk[e]] = b*NN + (int)(mine[e] & 0x1FFFULL);
}

// ================= fused attention: 6 points/block, 192 threads, 2 blocks/SM =================
struct SmemA {
    float Wp2[4096], Wt1[4096], Wt2[4096];
    float U[PRS*PAD];     // relu(pos) -> then VPE (v + pos_enc)
    float Y[PRS*PAD];     // a_in -> relu -> scores (in-place)
    float Res[PTS*64];
    int   Idx[PRS];
};

// 4x8 tile via packed fp32x2 FMA (fma.rn.f32x2 — two IEEE fp32 FMAs per issue).
// Thread owns rows pg + 24*r (strided -> conflict-free x loads); cols hg*8..+7 as 4 pairs.
__device__ __forceinline__ void gemm4x8(const float* __restrict__ X, const float* __restrict__ W,
                                        int pg, int hg, float acc[4][8]) {
    unsigned long long a2[4][4];
    #pragma unroll
    for (int r = 0; r < 4; r++)
        #pragma unroll
        for (int c = 0; c < 4; c++) a2[r][c] = 0ULL;   // (0.0f, 0.0f)
    const float* wb = W + hg*8;
    #pragma unroll 2
    for (int i4 = 0; i4 < 16; i4++) {
        float xa[4][4];
        #pragma unroll
        for (int r = 0; r < 4; r++)
            *(float4*)xa[r] = *(const float4*)(X + (pg + 24*r)*PAD + i4*4);
        #pragma unroll
        for (int ii = 0; ii < 4; ii++) {
            int i = i4*4 + ii;
            ulonglong2 w01 = *(const ulonglong2*)(wb + i*64);       // cols 0-3 as 2 pairs
            ulonglong2 w23 = *(const ulonglong2*)(wb + i*64 + 4);   // cols 4-7 as 2 pairs
            unsigned long long wv[4] = {w01.x, w01.y, w23.x, w23.y};
            #pragma unroll
            for (int r = 0; r < 4; r++) {
                unsigned long long xd;
                asm("mov.b64 %0, {%1, %1};" : "=l"(xd) : "r"(__float_as_uint(xa[r][ii])));
                #pragma unroll
                for (int c = 0; c < 4; c++)
                    asm("fma.rn.f32x2 %0, %1, %2, %0;" : "+l"(a2[r][c]) : "l"(xd), "l"(wv[c]));
            }
        }
    }
    #pragma unroll
    for (int r = 0; r < 4; r++)
        #pragma unroll
        for (int c = 0; c < 4; c++) {
            unsigned lo, hi;
            asm("mov.b64 {%0, %1}, %2;" : "=r"(lo), "=r"(hi) : "l"(a2[r][c]));
            acc[r][2*c]     = __uint_as_float(lo);
            acc[r][2*c + 1] = __uint_as_float(hi);
        }
}

__global__ __launch_bounds__(192, 2) void attn_kernel(
    const float* __restrict__ features,
    const float* __restrict__ bp1,
    const float* __restrict__ Wp2, const float* __restrict__ bp2,
    const float* __restrict__ Wt1, const float* __restrict__ bt1,
    const float* __restrict__ Wt2, const float* __restrict__ bt2,
    const float* __restrict__ Wa,  const float* __restrict__ ba,
    float* __restrict__ out) {
    extern __shared__ char smem_raw[];
    SmemA* sm = (SmemA*)smem_raw;
    int tid = threadIdx.x;        // 192
    int base = blockIdx.x * PTS;  // 6 points / block (last block partial)

    for (int i = tid; i < 1024; i += 192) {
        ((float4*)sm->Wp2)[i] = __ldg(((const float4*)Wp2) + i);
        ((float4*)sm->Wt1)[i] = __ldg(((const float4*)Wt1) + i);
        ((float4*)sm->Wt2)[i] = __ldg(((const float4*)Wt2) + i);
    }
    if (tid < PRS) {
        int prow = min(base + (tid >> 4), NP-1);
        sm->Idx[tid] = g_idx[(size_t)prow*16 + (tid & 15)];
    }
    __syncthreads();

    // ---- U[pair][i] = relu((A[n]+bp1) - A[j]) ----
    #pragma unroll
    for (int it = 0; it < 8; it++) {
        int flat = it*192 + tid;          // 0..1535
        int pair = flat >> 4, c4 = flat & 15;
        int prow = min(base + (pair >> 4), NP-1);
        int g = sm->Idx[pair];
        float4 an = __ldg(((const float4*)(g_A + (size_t)prow*64)) + c4);
        float4 bb = __ldg(((const float4*)bp1) + c4);
        float4 aj = __ldg(((const float4*)(g_A + (size_t)g*64)) + c4);
        float4 u;
        u.x = fmaxf(an.x + bb.x - aj.x, 0.f);
        u.y = fmaxf(an.y + bb.y - aj.y, 0.f);
        u.z = fmaxf(an.z + bb.z - aj.z, 0.f);
        u.w = fmaxf(an.w + bb.w - aj.w, 0.f);
        *(float4*)(sm->U + pair*PAD + c4*4) = u;
    }
    __syncthreads();

    int pg = tid >> 3;   // 0..23, rows pg + 24*r
    int hg = tid & 7;    // cols hg*8 .. +7
    float acc[4][8];

    // ---- GEMM1: pe = U @ Wp2 + bp2 ; Y = q - k + pe ; U := v + pe ----
    gemm4x8(sm->U, sm->Wp2, pg, hg, acc);
    __syncthreads();
    {
        float4 b0 = __ldg(((const float4*)bp2) + hg*2);
        float4 b1 = __ldg(((const float4*)bp2) + hg*2 + 1);
        float bb[8] = {b0.x, b0.y, b0.z, b0.w, b1.x, b1.y, b1.z, b1.w};
        #pragma unroll
        for (int r = 0; r < 4; r++) {
            int pair = pg + 24*r;
            int prow = min(base + (pair >> 4), NP-1);
            const float4* qp = (const float4*)(g_X + (size_t)prow*192) + hg*2;
            float4 q0 = __ldg(qp), q1 = __ldg(qp + 1);
            float qf[8] = {q0.x, q0.y, q0.z, q0.w, q1.x, q1.y, q1.z, q1.w};
            int g = sm->Idx[pair];
            const float4* kp = (const float4*)(g_X + (size_t)g*192 + 64) + hg*2;
            const float4* vp = (const float4*)(g_X + (size_t)g*192 + 128) + hg*2;
            float4 k0 = __ldg(kp), k1 = __ldg(kp + 1);
            float4 v0 = __ldg(vp), v1 = __ldg(vp + 1);
            float kf[8] = {k0.x, k0.y, k0.z, k0.w, k1.x, k1.y, k1.z, k1.w};
            float vf[8] = {v0.x, v0.y, v0.z, v0.w, v1.x, v1.y, v1.z, v1.w};
            float yv[8], uv[8];
            #pragma unroll
            for (int c = 0; c < 8; c++) {
                float pe = acc[r][c] + bb[c];
                yv[c] = qf[c] - kf[c] + pe;
                uv[c] = vf[c] + pe;
            }
            float* yb = sm->Y + pair*PAD + hg*8;
            float* ub = sm->U + pair*PAD + hg*8;
            *(float4*)yb       = make_float4(yv[0], yv[1], yv[2], yv[3]);
            *(float4*)(yb + 4) = make_float4(yv[4], yv[5], yv[6], yv[7]);
            *(float4*)ub       = make_float4(uv[0], uv[1], uv[2], uv[3]);
            *(float4*)(ub + 4) = make_float4(uv[4], uv[5], uv[6], uv[7]);
        }
    }
    __syncthreads();

    // ---- GEMM2: Y := relu(Y @ Wt1 + bt1) ----
    gemm4x8(sm->Y, sm->Wt1, pg, hg, acc);
    __syncthreads();
    {
        float4 b0 = __ldg(((const float4*)bt1) + hg*2);
        float4 b1 = __ldg(((const float4*)bt1) + hg*2 + 1);
        float bb[8] = {b0.x, b0.y, b0.z, b0.w, b1.x, b1.y, b1.z, b1.w};
        #pragma unroll
        for (int r = 0; r < 4; r++) {
            float* yb = sm->Y + (pg + 24*r)*PAD + hg*8;
            float t[8];
            #pragma unroll
            for (int c = 0; c < 8; c++) t[c] = fmaxf(acc[r][c] + bb[c], 0.f);
            *(float4*)yb       = make_float4(t[0], t[1], t[2], t[3]);
            *(float4*)(yb + 4) = make_float4(t[4], t[5], t[6], t[7]);
        }
    }
    __syncthreads();

    // ---- GEMM3: Y := (Y @ Wt2 + bt2) / 8 ----
    gemm4x8(sm->Y, sm->Wt2, pg, hg, acc);
    __syncthreads();
    {
        float4 b0 = __ldg(((const float4*)bt2) + hg*2);
        float4 b1 = __ldg(((const float4*)bt2) + hg*2 + 1);
        float bb[8] = {b0.x, b0.y, b0.z, b0.w, b1.x, b1.y, b1.z, b1.w};
        #pragma unroll
        for (int r = 0; r < 4; r++) {
            float* yb = sm->Y + (pg + 24*r)*PAD + hg*8;
            float t[8];
            #pragma unroll
            for (int c = 0; c < 8; c++) t[c] = (acc[r][c] + bb[c]) * 0.125f;
            *(float4*)yb       = make_float4(t[0], t[1], t[2], t[3]);
            *(float4*)(yb + 4) = make_float4(t[4], t[5], t[6], t[7]);
        }
    }
    __syncthreads();

    // ---- softmax over j + weighted sum with VPE ----
    #pragma unroll
    for (int e = tid; e < PTS*64; e += 192) {
        int p = e >> 6, h = e & 63;
        float m = -finf();
        #pragma unroll
        for (int j = 0; j < 16; j++)
            m = fmaxf(m, sm->Y[(p*16 + j)*PAD + h]);
        float num = 0.f, den = 0.f;
        #pragma unroll
        for (int j = 0; j < 16; j++) {
            float ex = __expf(sm->Y[(p*16 + j)*PAD + h] - m);
            den += ex;
            num = fmaf(ex, sm->U[(p*16 + j)*PAD + h], num);
        }
        sm->Res[p*64 + h] = num / den;
    }
    __syncthreads();

    // ---- final: out = Res @ Wa + ba + features ----
    #pragma unroll
    for (int e = tid; e < PTS*64; e += 192) {
        int p = e >> 6, h = e & 63;
        int row = base + p;
        if (row < NP) {
            float a = 0.f;
            const float* wa = Wa + h;
            #pragma unroll 8
            for (int i = 0; i < 64; i++)
                a = fmaf(sm->Res[p*64 + i], __ldg(wa + i*64), a);
            out[(size_t)row*64 + h] = a + __ldg(ba + h) + __ldg(features + (size_t)row*64 + h);
        }
    }
}

// ================= launch =================
extern "C" void kernel_launch(void* const* d_in, const int* in_sizes, int n_in,
                              void* d_out, int out_size) {
    const float* xyzp     = (const float*)d_in[0];
    const float* features = (const float*)d_in[1];
    const float* Wk  = (const float*)d_in[2];
    const float* bk  = (const float*)d_in[3];
    const float* Wq  = (const float*)d_in[4];
    const float* Wks = (const float*)d_in[5];
    const float* Wv  = (const float*)d_in[6];
    const float* Wp1 = (const float*)d_in[7];
    const float* bp1 = (const float*)d_in[8];
    const float* Wp2 = (const float*)d_in[9];
    const float* bp2 = (const float*)d_in[10];
    const float* Wt1 = (const float*)d_in[11];
    const float* bt1 = (const float*)d_in[12];
    const float* Wt2 = (const float*)d_in[13];
    const float* bt2 = (const float*)d_in[14];
    const float* Wa  = (const float*)d_in[15];
    const float* ba  = (const float*)d_in[16];
    float* out = (float*)d_out;

    cudaFuncSetAttribute(transform_kernel, cudaFuncAttributeMaxDynamicSharedMemorySize,
                         (int)sizeof(SmemT));
    cudaFuncSetAttribute(attn_kernel, cudaFuncAttributeMaxDynamicSharedMemorySize,
                         (int)sizeof(SmemA));

    fold_kernel<<<16, 256>>>(Wk, bk, Wq, Wks, Wv);
    transform_kernel<<<NP/16, 192, sizeof(SmemT)>>>(features, xyzp, Wp1);
    knn_kernel<<<NP/16, 128>>>();
    int attn_grid = (NP + PTS - 1) / PTS;
    attn_kernel<<<attn_grid, 192, sizeof(SmemA)>>>(features, bp1, Wp2, bp2,
                                                   Wt1, bt1, Wt2, bt2, Wa, ba, out);
}

// round 13
// speedup vs baseline: 1.3499x; 1.3499x over previous
#include <cuda_runtime.h>

#define NB 2
#define NN 8192
#define NP (NB*NN)      // 16384 points total
#define KK 16
#define PAD 68          // row stride (floats) for attn stage buffers
#define PTS 6           // points per attn block
#define PRS (PTS*16)    // 96 pairs per attn block
#define CAPA 24         // knn append-buffer capacity per lane

// ---------------- scratch (device globals; no allocation allowed) ----------------
__device__ float g_Wall[64*192];      // folded [i][c]: c 0-63 -> q, 64-127 -> k, 128-191 -> v
__device__ float g_call[192];         // folded biases
__device__ float g_X[NP*192];         // per-point q|k|v, row stride 192
__device__ float g_A[NP*64];          // per-point xyzp @ Wp1 (no bias)
__device__ int   g_idx[NP*KK];        // global neighbor row indices
__device__ float4 g_pts[NP];          // (x, y, z, |xyz|^2)

__device__ __forceinline__ float finf() { return __int_as_float(0x7f800000); }

// ================= fold: Mq=Wk@Wq etc, cq=bk@Wq etc =================
__global__ void fold_kernel(const float* __restrict__ Wk, const float* __restrict__ bk,
                            const float* __restrict__ Wq, const float* __restrict__ Wks,
                            const float* __restrict__ Wv) {
    int e = blockIdx.x * 256 + threadIdx.x;   // grid 16 x 256 = 4096
    int i = e >> 6, h = e & 63;
    float sq = 0.f, sk = 0.f, sv = 0.f;
    #pragma unroll 4
    for (int k = 0; k < 64; k++) {
        float wk = Wk[i*64 + k];
        sq = fmaf(wk, Wq [k*64 + h], sq);
        sk = fmaf(wk, Wks[k*64 + h], sk);
        sv = fmaf(wk, Wv [k*64 + h], sv);
    }
    g_Wall[i*192 + h]        = sq;
    g_Wall[i*192 + 64 + h]   = sk;
    g_Wall[i*192 + 128 + h]  = sv;
    if (blockIdx.x == 0 && threadIdx.x < 192) {
        int sec = threadIdx.x >> 6, hh = threadIdx.x & 63;
        const float* W = (sec == 0) ? Wq : ((sec == 1) ? Wks : Wv);
        float s = 0.f;
        #pragma unroll 4
        for (int k = 0; k < 64; k++) s = fmaf(bk[k], W[k*64 + hh], s);
        g_call[threadIdx.x] = s;
    }
}

// ================= transform: g_X = F @ Wall + call ; g_A = xyzp @ Wp1 ; g_pts =================
struct SmemT {
    float feat[16*65];
    float W[64*192];
    float c[192];
    float Wp1[4*64];
};

__global__ __launch_bounds__(192) void transform_kernel(
    const float* __restrict__ features, const float* __restrict__ xyzp,
    const float* __restrict__ Wp1) {
    extern __shared__ char smem_raw[];
    SmemT* sm = (SmemT*)smem_raw;
    int tid = threadIdx.x;            // 192 threads
    int base = blockIdx.x * 16;       // 16 rows per block

    for (int i4 = tid; i4 < 64*192/4; i4 += 192)
        ((float4*)sm->W)[i4] = ((const float4*)g_Wall)[i4];
    if (tid < 192) sm->c[tid] = g_call[tid];
    if (tid < 64)  ((float4*)sm->Wp1)[tid] = ((const float4*)Wp1)[tid];
    for (int i4 = tid; i4 < 16*64/4; i4 += 192) {
        int r = i4 >> 4, cc = i4 & 15;
        float4 v = ((const float4*)(features + (size_t)(base + r)*64))[cc];
        float* d = sm->feat + r*65 + cc*4;
        d[0] = v.x; d[1] = v.y; d[2] = v.z; d[3] = v.w;
    }
    if (tid < 16) {
        float4 p = ((const float4*)xyzp)[base + tid];
        float s = fmaf(p.x, p.x, fmaf(p.y, p.y, p.z*p.z));
        g_pts[base + tid] = make_float4(p.x, p.y, p.z, s);
    }
    __syncthreads();

    int rg = tid / 24;
    int cg = tid % 24;
    float acc[2][8];
    #pragma unroll
    for (int r = 0; r < 2; r++)
        #pragma unroll
        for (int c = 0; c < 8; c++) acc[r][c] = 0.f;

    #pragma unroll 4
    for (int i = 0; i < 64; i++) {
        float x0 = sm->feat[(rg*2    )*65 + i];
        float x1 = sm->feat[(rg*2 + 1)*65 + i];
        float4 w0 = *(const float4*)(sm->W + i*192 + cg*8);
        float4 w1 = *(const float4*)(sm->W + i*192 + cg*8 + 4);
        float wv[8] = {w0.x, w0.y, w0.z, w0.w, w1.x, w1.y, w1.z, w1.w};
        #pragma unroll
        for (int c = 0; c < 8; c++) {
            acc[0][c] = fmaf(x0, wv[c], acc[0][c]);
            acc[1][c] = fmaf(x1, wv[c], acc[1][c]);
        }
    }
    #pragma unroll
    for (int r = 0; r < 2; r++) {
        int row = base + rg*2 + r;
        float4 o0, o1;
        o0.x = acc[r][0] + sm->c[cg*8 + 0];
        o0.y = acc[r][1] + sm->c[cg*8 + 1];
        o0.z = acc[r][2] + sm->c[cg*8 + 2];
        o0.w = acc[r][3] + sm->c[cg*8 + 3];
        o1.x = acc[r][4] + sm->c[cg*8 + 4];
        o1.y = acc[r][5] + sm->c[cg*8 + 5];
        o1.z = acc[r][6] + sm->c[cg*8 + 6];
        o1.w = acc[r][7] + sm->c[cg*8 + 7];
        *(float4*)(g_X + (size_t)row*192 + cg*8)     = o0;
        *(float4*)(g_X + (size_t)row*192 + cg*8 + 4) = o1;
    }

    for (int o = tid; o < 16*64; o += 192) {
        int r = o >> 6, h = o & 63;
        const float* xp = xyzp + (size_t)(base + r)*4;
        float a = xp[0] * sm->Wp1[0*64 + h];
        a = fmaf(xp[1], sm->Wp1[1*64 + h], a);
        a = fmaf(xp[2], sm->Wp1[2*64 + h], a);
        a = fmaf(xp[3], sm->Wp1[3*64 + h], a);
        g_A[(size_t)(base + r)*64 + h] = a;
    }
}

// ================= knn (R8/R11 version): branchless append-buffer + deferred compaction ===
__device__ __forceinline__ void knn_merge16(float bk[16], int bi[16], float f, int ix) {
    bool t = f < bk[0];
    bk[0] = t ? f : bk[0];
    bi[0] = t ? ix : bi[0];
    #pragma unroll
    for (int s = 0; s < 15; s++) {
        bool csw = bk[s] < bk[s+1];
        float hi = fmaxf(bk[s], bk[s+1]);
        float lo = fminf(bk[s], bk[s+1]);
        int ih = csw ? bi[s+1] : bi[s];
        int il = csw ? bi[s]   : bi[s+1];
        bk[s] = hi; bk[s+1] = lo;
        bi[s] = ih; bi[s+1] = il;
    }
}

__global__ __launch_bounds__(128) void knn_kernel() {
    __shared__ unsigned long long sB[CAPA*128];   // per-lane buffer, entry e at [e*128+tid]
    int tid  = threadIdx.x;                       // 128: 32 queries x 4 lanes
    int b    = blockIdx.x >> 8;                   // 256 blocks per batch
    int qloc = tid >> 2, sub = tid & 3;
    int n    = ((blockIdx.x & 255) << 5) + qloc;
    int row  = b*NN + n;
    float4 me = __ldg(&g_pts[row]);
    float xn = me.x, yn = me.y, zn = me.z;
    const float4* src = g_pts + (size_t)b*NN + (sub << 11);  // lane's 2048 range
    int jg0 = sub << 11;

    float bk[16];
    int   bi[16];
    #pragma unroll
    for (int s = 0; s < 16; s++) { bk[s] = finf(); bi[s] = 0; }
    float tau = finf();
    int cnt = 0;

    for (int ch = 0; ch < 256; ch++) {
        #pragma unroll
        for (int u = 0; u < 8; u++) {
            int j = (ch << 3) + u;
            float4 c = __ldg(src + j);
            float f = fmaf(-2.f, fmaf(xn, c.x, fmaf(yn, c.y, zn*c.z)), c.w);
            ((float2*)sB)[cnt*128 + tid] = make_float2(f, __int_as_float(jg0 + j));
            cnt += (f <= tau) ? 1 : 0;
        }
        if (__ballot_sync(0xffffffffu, cnt > 16)) {
            for (int e = 0; e < cnt; e++) {
                float2 en = ((float2*)sB)[e*128 + tid];
                knn_merge16(bk, bi, en.x, __float_as_int(en.y));
            }
            cnt = 0;
            float t0 = fminf(bk[0], __shfl_xor_sync(0xffffffffu, bk[0], 1));
            tau = fminf(t0, __shfl_xor_sync(0xffffffffu, t0, 2));
        }
    }
    // final compaction (uniform)
    for (int e = 0; e < cnt; e++) {
        float2 en = ((float2*)sB)[e*128 + tid];
        knn_merge16(bk, bi, en.x, __float_as_int(en.y));
    }

    // pack final 16 as sortable u64 and publish for merge
    unsigned long long mine[16];
    #pragma unroll
    for (int s = 0; s < 16; s++) {
        unsigned u = __float_as_uint(bk[s]);
        u ^= ((unsigned)((int)u >> 31)) | 0x80000000u;
        mine[s] = ((unsigned long long)u << 13) | (unsigned)bi[s];
        sB[s*128 + tid] = mine[s];
    }
    __syncwarp();

    // exact rank of my 16 among the query's 64 (distinct: disjoint idx ranges)
    int rk[16];
    #pragma unroll
    for (int s = 0; s < 16; s++) rk[s] = 0;
    int lbase = tid & ~3;
    #pragma unroll 4
    for (int o = 0; o < 64; o++) {
        unsigned long long ov = sB[(o >> 2)*128 + lbase + (o & 3)];
        #pragma unroll
        for (int e = 0; e < 16; e++) rk[e] += (ov < mine[e]) ? 1 : 0;
    }
    #pragma unroll
    for (int e = 0; e < 16; e++)
        if (rk[e] < 16)
            g_idx[(size_t)row*16 + rk[e]] = b*NN + (int)(mine[e] & 0x1FFFULL);
}

// ================= fused attention: 6 points/block, 192 threads, 2 blocks/SM =================
// Phase chain gemm1->epi1->gemm2->epi2->gemm3 is WARP-LOCAL: thread (pg,hg) reads rows
// pg+24r written only by threads (pg, hg'=0..7) of the same warp -> __syncwarp suffices.
// Cross-warp edges (U-init -> gemm1, epi3 -> softmax, softmax -> final) keep __syncthreads.
struct SmemA {
    float Wp2[4096], Wt1[4096], Wt2[4096];
    float U[PRS*PAD];     // relu(pos) -> then VPE (v + pos_enc)
    float Y[PRS*PAD];     // a_in -> relu -> scores (in-place)
    float Res[PTS*64];
    int   Idx[PRS];
};

// 4x8 tile via packed fp32x2 FMA (fma.rn.f32x2 — two IEEE fp32 FMAs per issue).
// Thread owns rows pg + 24*r (strided -> conflict-free x loads); cols hg*8..+7 as 4 pairs.
__device__ __forceinline__ void gemm4x8(const float* __restrict__ X, const float* __restrict__ W,
                                        int pg, int hg, float acc[4][8]) {
    unsigned long long a2[4][4];
    #pragma unroll
    for (int r = 0; r < 4; r++)
        #pragma unroll
        for (int c = 0; c < 4; c++) a2[r][c] = 0ULL;   // (0.0f, 0.0f)
    const float* wb = W + hg*8;
    #pragma unroll 2
    for (int i4 = 0; i4 < 16; i4++) {
        float xa[4][4];
        #pragma unroll
        for (int r = 0; r < 4; r++)
            *(float4*)xa[r] = *(const float4*)(X + (pg + 24*r)*PAD + i4*4);
        #pragma unroll
        for (int ii = 0; ii < 4; ii++) {
            int i = i4*4 + ii;
            ulonglong2 w01 = *(const ulonglong2*)(wb + i*64);       // cols 0-3 as 2 pairs
            ulonglong2 w23 = *(const ulonglong2*)(wb + i*64 + 4);   // cols 4-7 as 2 pairs
            unsigned long long wv[4] = {w01.x, w01.y, w23.x, w23.y};
            #pragma unroll
            for (int r = 0; r < 4; r++) {
                unsigned long long xd;
                asm("mov.b64 %0, {%1, %1};" : "=l"(xd) : "r"(__float_as_uint(xa[r][ii])));
                #pragma unroll
                for (int c = 0; c < 4; c++)
                    asm("fma.rn.f32x2 %0, %1, %2, %0;" : "+l"(a2[r][c]) : "l"(xd), "l"(wv[c]));
            }
        }
    }
    #pragma unroll
    for (int r = 0; r < 4; r++)
        #pragma unroll
        for (int c = 0; c < 4; c++) {
            unsigned lo, hi;
            asm("mov.b64 {%0, %1}, %2;" : "=r"(lo), "=r"(hi) : "l"(a2[r][c]));
            acc[r][2*c]     = __uint_as_float(lo);
            acc[r][2*c + 1] = __uint_as_float(hi);
        }
}

__global__ __launch_bounds__(192, 2) void attn_kernel(
    const float* __restrict__ features,
    const float* __restrict__ bp1,
    const float* __restrict__ Wp2, const float* __restrict__ bp2,
    const float* __restrict__ Wt1, const float* __restrict__ bt1,
    const float* __restrict__ Wt2, const float* __restrict__ bt2,
    const float* __restrict__ Wa,  const float* __restrict__ ba,
    float* __restrict__ out) {
    extern __shared__ char smem_raw[];
    SmemA* sm = (SmemA*)smem_raw;
    int tid = threadIdx.x;        // 192
    int base = blockIdx.x * PTS;  // 6 points / block (last block partial)

    for (int i = tid; i < 1024; i += 192) {
        ((float4*)sm->Wp2)[i] = __ldg(((const float4*)Wp2) + i);
        ((float4*)sm->Wt1)[i] = __ldg(((const float4*)Wt1) + i);
        ((float4*)sm->Wt2)[i] = __ldg(((const float4*)Wt2) + i);
    }
    if (tid < PRS) {
        int prow = min(base + (tid >> 4), NP-1);
        sm->Idx[tid] = g_idx[(size_t)prow*16 + (tid & 15)];
    }
    __syncthreads();

    // ---- U[pair][i] = relu((A[n]+bp1) - A[j]) ----  (cross-warp writers)
    #pragma unroll
    for (int it = 0; it < 8; it++) {
        int flat = it*192 + tid;          // 0..1535
        int pair = flat >> 4, c4 = flat & 15;
        int prow = min(base + (pair >> 4), NP-1);
        int g = sm->Idx[pair];
        float4 an = __ldg(((const float4*)(g_A + (size_t)prow*64)) + c4);
        float4 bb = __ldg(((const float4*)bp1) + c4);
        float4 aj = __ldg(((const float4*)(g_A + (size_t)g*64)) + c4);
        float4 u;
        u.x = fmaxf(an.x + bb.x - aj.x, 0.f);
        u.y = fmaxf(an.y + bb.y - aj.y, 0.f);
        u.z = fmaxf(an.z + bb.z - aj.z, 0.f);
        u.w = fmaxf(an.w + bb.w - aj.w, 0.f);
        *(float4*)(sm->U + pair*PAD + c4*4) = u;
    }
    __syncthreads();   // cross-warp: U rows written by scattered tids

    int pg = tid >> 3;   // 0..23, rows pg + 24*r
    int hg = tid & 7;    // cols hg*8 .. +7
    float acc[4][8];

    // ---- GEMM1: pe = U @ Wp2 + bp2 ; Y = q - k + pe ; U := v + pe ----
    gemm4x8(sm->U, sm->Wp2, pg, hg, acc);
    __syncwarp();      // warp-local: U rows pg+24r read/written within warp
    {
        float4 b0 = __ldg(((const float4*)bp2) + hg*2);
        float4 b1 = __ldg(((const float4*)bp2) + hg*2 + 1);
        float bb[8] = {b0.x, b0.y, b0.z, b0.w, b1.x, b1.y, b1.z, b1.w};
        #pragma unroll
        for (int r = 0; r < 4; r++) {
            int pair = pg + 24*r;
            int prow = min(base + (pair >> 4), NP-1);
            const float4* qp = (const float4*)(g_X + (size_t)prow*192) + hg*2;
            float4 q0 = __ldg(qp), q1 = __ldg(qp + 1);
            float qf[8] = {q0.x, q0.y, q0.z, q0.w, q1.x, q1.y, q1.z, q1.w};
            int g = sm->Idx[pair];
            const float4* kp = (const float4*)(g_X + (size_t)g*192 + 64) + hg*2;
            const float4* vp = (const float4*)(g_X + (size_t)g*192 + 128) + hg*2;
            float4 k0 = __ldg(kp), k1 = __ldg(kp + 1);
            float4 v0 = __ldg(vp), v1 = __ldg(vp + 1);
            float kf[8] = {k0.x, k0.y, k0.z, k0.w, k1.x, k1.y, k1.z, k1.w};
            float vf[8] = {v0.x, v0.y, v0.z, v0.w, v1.x, v1.y, v1.z, v1.w};
            float yv[8], uv[8];
            #pragma unroll
            for (int c = 0; c < 8; c++) {
                float pe = acc[r][c] + bb[c];
                yv[c] = qf[c] - kf[c] + pe;
                uv[c] = vf[c] + pe;
            }
            float* yb = sm->Y + pair*PAD + hg*8;
            float* ub = sm->U + pair*PAD + hg*8;
            *(float4*)yb       = make_float4(yv[0], yv[1], yv[2], yv[3]);
            *(float4*)(yb + 4) = make_float4(yv[4], yv[5], yv[6], yv[7]);
            *(float4*)ub       = make_float4(uv[0], uv[1], uv[2], uv[3]);
            *(float4*)(ub + 4) = make_float4(uv[4], uv[5], uv[6], uv[7]);
        }
    }
    __syncwarp();      // warp-local: Y rows pg+24r feed same warp's gemm2

    // ---- GEMM2: Y := relu(Y @ Wt1 + bt1) ----
    gemm4x8(sm->Y, sm->Wt1, pg, hg, acc);
    __syncwarp();
    {
        float4 b0 = __ldg(((const float4*)bt1) + hg*2);
        float4 b1 = __ldg(((const float4*)bt1) + hg*2 + 1);
        float bb[8] = {b0.x, b0.y, b0.z, b0.w, b1.x, b1.y, b1.z, b1.w};
        #pragma unroll
        for (int r = 0; r < 4; r++) {
            float* yb = sm->Y + (pg + 24*r)*PAD + hg*8;
            float t[8];
            #pragma unroll
            for (int c = 0; c < 8; c++) t[c] = fmaxf(acc[r][c] + bb[c], 0.f);
            *(float4*)yb       = make_float4(t[0], t[1], t[2], t[3]);
            *(float4*)(yb + 4) = make_float4(t[4], t[5], t[6], t[7]);
        }
    }
    __syncwarp();

    // ---- GEMM3: Y := (Y @ Wt2 + bt2) / 8 ----
    gemm4x8(sm->Y, sm->Wt2, pg, hg, acc);
    __syncwarp();
    {
        float4 b0 = __ldg(((const float4*)bt2) + hg*2);
        float4 b1 = __ldg(((const float4*)bt2) + hg*2 + 1);
        float bb[8] = {b0.x, b0.y, b0.z, b0.w, b1.x, b1.y, b1.z, b1.w};
        #pragma unroll
        for (int r = 0; r < 4; r++) {
            float* yb = sm->Y + (pg + 24*r)*PAD + hg*8;
            float t[8];
            #pragma unroll
            for (int c = 0; c < 8; c++) t[c] = (acc[r][c] + bb[c]) * 0.125f;
            *(float4*)yb       = make_float4(t[0], t[1], t[2], t[3]);
            *(float4*)(yb + 4) = make_float4(t[4], t[5], t[6], t[7]);
        }
    }
    __syncthreads();   // cross-warp: softmax reads all 16 rows of each point

    // ---- softmax over j + weighted sum with VPE ----
    #pragma unroll
    for (int e = tid; e < PTS*64; e += 192) {
        int p = e >> 6, h = e & 63;
        float m = -finf();
        #pragma unroll
        for (int j = 0; j < 16; j++)
            m = fmaxf(m, sm->Y[(p*16 + j)*PAD + h]);
        float num = 0.f, den = 0.f;
        #pragma unroll
        for (int j = 0; j < 16; j++) {
            float ex = __expf(sm->Y[(p*16 + j)*PAD + h] - m);
            den += ex;
            num = fmaf(ex, sm->U[(p*16 + j)*PAD + h], num);
        }
        sm->Res[p*64 + h] = num / den;
    }
    __syncthreads();   // cross-warp: final GEMV reads full Res rows

    // ---- final: out = Res @ Wa + ba + features ----
    #pragma unroll
    for (int e = tid; e < PTS*64; e += 192) {
        int p = e >> 6, h = e & 63;
        int row = base + p;
        if (row < NP) {
            float a = 0.f;
            const float* wa = Wa + h;
            #pragma unroll 8
            for (int i = 0; i < 64; i++)
                a = fmaf(sm->Res[p*64 + i], __ldg(wa + i*64), a);
            out[(size_t)row*64 + h] = a + __ldg(ba + h) + __ldg(features + (size_t)row*64 + h);
        }
    }
}

// ================= launch =================
extern "C" void kernel_launch(void* const* d_in, const int* in_sizes, int n_in,
                              void* d_out, int out_size) {
    const float* xyzp     = (const float*)d_in[0];
    const float* features = (const float*)d_in[1];
    const float* Wk  = (const float*)d_in[2];
    const float* bk  = (const float*)d_in[3];
    const float* Wq  = (const float*)d_in[4];
    const float* Wks = (const float*)d_in[5];
    const float* Wv  = (const float*)d_in[6];
    const float* Wp1 = (const float*)d_in[7];
    const float* bp1 = (const float*)d_in[8];
    const float* Wp2 = (const float*)d_in[9];
    const float* bp2 = (const float*)d_in[10];
    const float* Wt1 = (const float*)d_in[11];
    const float* bt1 = (const float*)d_in[12];
    const float* Wt2 = (const float*)d_in[13];
    const float* bt2 = (const float*)d_in[14];
    const float* Wa  = (const float*)d_in[15];
    const float* ba  = (const float*)d_in[16];
    float* out = (float*)d_out;

    cudaFuncSetAttribute(transform_kernel, cudaFuncAttributeMaxDynamicSharedMemorySize,
                         (int)sizeof(SmemT));
    cudaFuncSetAttribute(attn_kernel, cudaFuncAttributeMaxDynamicSharedMemorySize,
                         (int)sizeof(SmemA));

    fold_kernel<<<16, 256>>>(Wk, bk, Wq, Wks, Wv);
    transform_kernel<<<NP/16, 192, sizeof(SmemT)>>>(features, xyzp, Wp1);
    knn_kernel<<<512, 128>>>();
    int attn_grid = (NP + PTS - 1) / PTS;
    attn_kernel<<<attn_grid, 192, sizeof(SmemA)>>>(features, bp1, Wp2, bp2,
                                                   Wt1, bt1, Wt2, bt2, Wa, ba, out);
}

// round 14
// speedup vs baseline: 1.3713x; 1.0159x over previous
#include <cuda_runtime.h>

#define NB 2
#define NN 8192
#define NP (NB*NN)      // 16384 points total
#define KK 16
#define PAD 68          // row stride (floats) for attn stage buffers
#define PTS 6           // points per attn block
#define PRS (PTS*16)    // 96 pairs per attn block
#define CAPA 24         // knn append-buffer capacity per lane

// ---------------- scratch (device globals; no allocation allowed) ----------------
__device__ float g_Wall[64*192];      // folded [i][c]: c 0-63 -> q, 64-127 -> k, 128-191 -> v
__device__ float g_call[192];         // folded biases
__device__ float g_X[NP*192];         // per-point q|k|v, row stride 192
__device__ float g_A[NP*64];          // per-point xyzp @ Wp1 (no bias)
__device__ int   g_idx[NP*KK];        // global neighbor row indices
__device__ float4 g_pts[NP];          // (x, y, z, |xyz|^2)

__device__ __forceinline__ float finf() { return __int_as_float(0x7f800000); }

// ================= fold: Mq=Wk@Wq etc, cq=bk@Wq etc =================
__global__ void fold_kernel(const float* __restrict__ Wk, const float* __restrict__ bk,
                            const float* __restrict__ Wq, const float* __restrict__ Wks,
                            const float* __restrict__ Wv) {
    int e = blockIdx.x * 256 + threadIdx.x;   // grid 16 x 256 = 4096
    int i = e >> 6, h = e & 63;
    float sq = 0.f, sk = 0.f, sv = 0.f;
    #pragma unroll 4
    for (int k = 0; k < 64; k++) {
        float wk = Wk[i*64 + k];
        sq = fmaf(wk, Wq [k*64 + h], sq);
        sk = fmaf(wk, Wks[k*64 + h], sk);
        sv = fmaf(wk, Wv [k*64 + h], sv);
    }
    g_Wall[i*192 + h]        = sq;
    g_Wall[i*192 + 64 + h]   = sk;
    g_Wall[i*192 + 128 + h]  = sv;
    if (blockIdx.x == 0 && threadIdx.x < 192) {
        int sec = threadIdx.x >> 6, hh = threadIdx.x & 63;
        const float* W = (sec == 0) ? Wq : ((sec == 1) ? Wks : Wv);
        float s = 0.f;
        #pragma unroll 4
        for (int k = 0; k < 64; k++) s = fmaf(bk[k], W[k*64 + hh], s);
        g_call[threadIdx.x] = s;
    }
}

// ================= transform: g_X = F @ Wall + call ; g_A = xyzp @ Wp1 ; g_pts =================
struct SmemT {
    float feat[16*65];
    float W[64*192];
    float c[192];
    float Wp1[4*64];
};

__global__ __launch_bounds__(192) void transform_kernel(
    const float* __restrict__ features, const float* __restrict__ xyzp,
    const float* __restrict__ Wp1) {
    extern __shared__ char smem_raw[];
    SmemT* sm = (SmemT*)smem_raw;
    int tid = threadIdx.x;            // 192 threads
    int base = blockIdx.x * 16;       // 16 rows per block

    for (int i4 = tid; i4 < 64*192/4; i4 += 192)
        ((float4*)sm->W)[i4] = ((const float4*)g_Wall)[i4];
    if (tid < 192) sm->c[tid] = g_call[tid];
    if (tid < 64)  ((float4*)sm->Wp1)[tid] = ((const float4*)Wp1)[tid];
    for (int i4 = tid; i4 < 16*64/4; i4 += 192) {
        int r = i4 >> 4, cc = i4 & 15;
        float4 v = ((const float4*)(features + (size_t)(base + r)*64))[cc];
        float* d = sm->feat + r*65 + cc*4;
        d[0] = v.x; d[1] = v.y; d[2] = v.z; d[3] = v.w;
    }
    if (tid < 16) {
        float4 p = ((const float4*)xyzp)[base + tid];
        float s = fmaf(p.x, p.x, fmaf(p.y, p.y, p.z*p.z));
        g_pts[base + tid] = make_float4(p.x, p.y, p.z, s);
    }
    __syncthreads();

    int rg = tid / 24;
    int cg = tid % 24;
    float acc[2][8];
    #pragma unroll
    for (int r = 0; r < 2; r++)
        #pragma unroll
        for (int c = 0; c < 8; c++) acc[r][c] = 0.f;

    #pragma unroll 4
    for (int i = 0; i < 64; i++) {
        float x0 = sm->feat[(rg*2    )*65 + i];
        float x1 = sm->feat[(rg*2 + 1)*65 + i];
        float4 w0 = *(const float4*)(sm->W + i*192 + cg*8);
        float4 w1 = *(const float4*)(sm->W + i*192 + cg*8 + 4);
        float wv[8] = {w0.x, w0.y, w0.z, w0.w, w1.x, w1.y, w1.z, w1.w};
        #pragma unroll
        for (int c = 0; c < 8; c++) {
            acc[0][c] = fmaf(x0, wv[c], acc[0][c]);
            acc[1][c] = fmaf(x1, wv[c], acc[1][c]);
        }
    }
    #pragma unroll
    for (int r = 0; r < 2; r++) {
        int row = base + rg*2 + r;
        float4 o0, o1;
        o0.x = acc[r][0] + sm->c[cg*8 + 0];
        o0.y = acc[r][1] + sm->c[cg*8 + 1];
        o0.z = acc[r][2] + sm->c[cg*8 + 2];
        o0.w = acc[r][3] + sm->c[cg*8 + 3];
        o1.x = acc[r][4] + sm->c[cg*8 + 4];
        o1.y = acc[r][5] + sm->c[cg*8 + 5];
        o1.z = acc[r][6] + sm->c[cg*8 + 6];
        o1.w = acc[r][7] + sm->c[cg*8 + 7];
        *(float4*)(g_X + (size_t)row*192 + cg*8)     = o0;
        *(float4*)(g_X + (size_t)row*192 + cg*8 + 4) = o1;
    }

    for (int o = tid; o < 16*64; o += 192) {
        int r = o >> 6, h = o & 63;
        const float* xp = xyzp + (size_t)(base + r)*4;
        float a = xp[0] * sm->Wp1[0*64 + h];
        a = fmaf(xp[1], sm->Wp1[1*64 + h], a);
        a = fmaf(xp[2], sm->Wp1[2*64 + h], a);
        a = fmaf(xp[3], sm->Wp1[3*64 + h], a);
        g_A[(size_t)(base + r)*64 + h] = a;
    }
}

// ================= knn (R8/R11 version — FROZEN): branchless append buffer ===============
__device__ __forceinline__ void knn_merge16(float bk[16], int bi[16], float f, int ix) {
    bool t = f < bk[0];
    bk[0] = t ? f : bk[0];
    bi[0] = t ? ix : bi[0];
    #pragma unroll
    for (int s = 0; s < 15; s++) {
        bool csw = bk[s] < bk[s+1];
        float hi = fmaxf(bk[s], bk[s+1]);
        float lo = fminf(bk[s], bk[s+1]);
        int ih = csw ? bi[s+1] : bi[s];
        int il = csw ? bi[s]   : bi[s+1];
        bk[s] = hi; bk[s+1] = lo;
        bi[s] = ih; bi[s+1] = il;
    }
}

__global__ __launch_bounds__(128) void knn_kernel() {
    __shared__ unsigned long long sB[CAPA*128];   // per-lane buffer, entry e at [e*128+tid]
    int tid  = threadIdx.x;                       // 128: 32 queries x 4 lanes
    int b    = blockIdx.x >> 8;                   // 256 blocks per batch
    int qloc = tid >> 2, sub = tid & 3;
    int n    = ((blockIdx.x & 255) << 5) + qloc;
    int row  = b*NN + n;
    float4 me = __ldg(&g_pts[row]);
    float xn = me.x, yn = me.y, zn = me.z;
    const float4* src = g_pts + (size_t)b*NN + (sub << 11);  // lane's 2048 range
    int jg0 = sub << 11;

    float bk[16];
    int   bi[16];
    #pragma unroll
    for (int s = 0; s < 16; s++) { bk[s] = finf(); bi[s] = 0; }
    float tau = finf();
    int cnt = 0;

    for (int ch = 0; ch < 256; ch++) {
        #pragma unroll
        for (int u = 0; u < 8; u++) {
            int j = (ch << 3) + u;
            float4 c = __ldg(src + j);
            float f = fmaf(-2.f, fmaf(xn, c.x, fmaf(yn, c.y, zn*c.z)), c.w);
            ((float2*)sB)[cnt*128 + tid] = make_float2(f, __int_as_float(jg0 + j));
            cnt += (f <= tau) ? 1 : 0;
        }
        if (__ballot_sync(0xffffffffu, cnt > 16)) {
            for (int e = 0; e < cnt; e++) {
                float2 en = ((float2*)sB)[e*128 + tid];
                knn_merge16(bk, bi, en.x, __float_as_int(en.y));
            }
            cnt = 0;
            float t0 = fminf(bk[0], __shfl_xor_sync(0xffffffffu, bk[0], 1));
            tau = fminf(t0, __shfl_xor_sync(0xffffffffu, t0, 2));
        }
    }
    // final compaction (uniform)
    for (int e = 0; e < cnt; e++) {
        float2 en = ((float2*)sB)[e*128 + tid];
        knn_merge16(bk, bi, en.x, __float_as_int(en.y));
    }

    // pack final 16 as sortable u64 and publish for merge
    unsigned long long mine[16];
    #pragma unroll
    for (int s = 0; s < 16; s++) {
        unsigned u = __float_as_uint(bk[s]);
        u ^= ((unsigned)((int)u >> 31)) | 0x80000000u;
        mine[s] = ((unsigned long long)u << 13) | (unsigned)bi[s];
        sB[s*128 + tid] = mine[s];
    }
    __syncwarp();

    // exact rank of my 16 among the query's 64 (distinct: disjoint idx ranges)
    int rk[16];
    #pragma unroll
    for (int s = 0; s < 16; s++) rk[s] = 0;
    int lbase = tid & ~3;
    #pragma unroll 4
    for (int o = 0; o < 64; o++) {
        unsigned long long ov = sB[(o >> 2)*128 + lbase + (o & 3)];
        #pragma unroll
        for (int e = 0; e < 16; e++) rk[e] += (ov < mine[e]) ? 1 : 0;
    }
    #pragma unroll
    for (int e = 0; e < 16; e++)
        if (rk[e] < 16)
            g_idx[(size_t)row*16 + rk[e]] = b*NN + (int)(mine[e] & 0x1FFFULL);
}

// ================= fused attention: 6 points/block, 192 threads, 3 blocks/SM =================
// Single staged weight buffer: W holds Wp2 -> Wt1 -> Wt2 across the three GEMM phases.
// Weights total 48KB and stay L2/L1-hot, so per-phase reloads are cheap; smem drops to
// ~69KB -> 3 blocks/SM (4.5 warps/SMSP) for latency hiding on the LDS->FFMA2 chains.
struct SmemA {
    float W[4096];        // staged weight buffer (Wp2 / Wt1 / Wt2)
    float U[PRS*PAD];     // relu(pos) -> then VPE (v + pos_enc)
    float Y[PRS*PAD];     // a_in -> relu -> scores (in-place)
    float Res[PTS*64];
    int   Idx[PRS];
};

__device__ __forceinline__ void load_W(SmemA* sm, const float* __restrict__ src, int tid) {
    #pragma unroll
    for (int i = tid; i < 1024; i += 192)
        ((float4*)sm->W)[i] = __ldg(((const float4*)src) + i);
}

// 4x8 tile via packed fp32x2 FMA (fma.rn.f32x2 — two IEEE fp32 FMAs per issue).
// Thread owns rows pg + 24*r (strided -> conflict-free x loads); cols hg*8..+7 as 4 pairs.
__device__ __forceinline__ void gemm4x8(const float* __restrict__ X, const float* __restrict__ W,
                                        int pg, int hg, float acc[4][8]) {
    unsigned long long a2[4][4];
    #pragma unroll
    for (int r = 0; r < 4; r++)
        #pragma unroll
        for (int c = 0; c < 4; c++) a2[r][c] = 0ULL;   // (0.0f, 0.0f)
    const float* wb = W + hg*8;
    #pragma unroll 2
    for (int i4 = 0; i4 < 16; i4++) {
        float xa[4][4];
        #pragma unroll
        for (int r = 0; r < 4; r++)
            *(float4*)xa[r] = *(const float4*)(X + (pg + 24*r)*PAD + i4*4);
        #pragma unroll
        for (int ii = 0; ii < 4; ii++) {
            int i = i4*4 + ii;
            ulonglong2 w01 = *(const ulonglong2*)(wb + i*64);       // cols 0-3 as 2 pairs
            ulonglong2 w23 = *(const ulonglong2*)(wb + i*64 + 4);   // cols 4-7 as 2 pairs
            unsigned long long wv[4] = {w01.x, w01.y, w23.x, w23.y};
            #pragma unroll
            for (int r = 0; r < 4; r++) {
                unsigned long long xd;
                asm("mov.b64 %0, {%1, %1};" : "=l"(xd) : "r"(__float_as_uint(xa[r][ii])));
                #pragma unroll
                for (int c = 0; c < 4; c++)
                    asm("fma.rn.f32x2 %0, %1, %2, %0;" : "+l"(a2[r][c]) : "l"(xd), "l"(wv[c]));
            }
        }
    }
    #pragma unroll
    for (int r = 0; r < 4; r++)
        #pragma unroll
        for (int c = 0; c < 4; c++) {
            unsigned lo, hi;
            asm("mov.b64 {%0, %1}, %2;" : "=r"(lo), "=r"(hi) : "l"(a2[r][c]));
            acc[r][2*c]     = __uint_as_float(lo);
            acc[r][2*c + 1] = __uint_as_float(hi);
        }
}

__global__ __launch_bounds__(192, 3) void attn_kernel(
    const float* __restrict__ features,
    const float* __restrict__ bp1,
    const float* __restrict__ Wp2, const float* __restrict__ bp2,
    const float* __restrict__ Wt1, const float* __restrict__ bt1,
    const float* __restrict__ Wt2, const float* __restrict__ bt2,
    const float* __restrict__ Wa,  const float* __restrict__ ba,
    float* __restrict__ out) {
    extern __shared__ char smem_raw[];
    SmemA* sm = (SmemA*)smem_raw;
    int tid = threadIdx.x;        // 192
    int base = blockIdx.x * PTS;  // 6 points / block (last block partial)

    load_W(sm, Wp2, tid);         // stage 1 weights
    if (tid < PRS) {
        int prow = min(base + (tid >> 4), NP-1);
        sm->Idx[tid] = g_idx[(size_t)prow*16 + (tid & 15)];
    }
    __syncthreads();

    // ---- U[pair][i] = relu((A[n]+bp1) - A[j]) ----  (cross-warp writers)
    #pragma unroll
    for (int it = 0; it < 8; it++) {
        int flat = it*192 + tid;          // 0..1535
        int pair = flat >> 4, c4 = flat & 15;
        int prow = min(base + (pair >> 4), NP-1);
        int g = sm->Idx[pair];
        float4 an = __ldg(((const float4*)(g_A + (size_t)prow*64)) + c4);
        float4 bb = __ldg(((const float4*)bp1) + c4);
        float4 aj = __ldg(((const float4*)(g_A + (size_t)g*64)) + c4);
        float4 u;
        u.x = fmaxf(an.x + bb.x - aj.x, 0.f);
        u.y = fmaxf(an.y + bb.y - aj.y, 0.f);
        u.z = fmaxf(an.z + bb.z - aj.z, 0.f);
        u.w = fmaxf(an.w + bb.w - aj.w, 0.f);
        *(float4*)(sm->U + pair*PAD + c4*4) = u;
    }
    __syncthreads();   // cross-warp: U rows written by scattered tids

    int pg = tid >> 3;   // 0..23, rows pg + 24*r
    int hg = tid & 7;    // cols hg*8 .. +7
    float acc[4][8];

    // ---- GEMM1: pe = U @ Wp2 + bp2 ; Y = q - k + pe ; U := v + pe ----
    gemm4x8(sm->U, sm->W, pg, hg, acc);
    __syncwarp();      // warp-local: U rows pg+24r read/written within warp
    {
        float4 b0 = __ldg(((const float4*)bp2) + hg*2);
        float4 b1 = __ldg(((const float4*)bp2) + hg*2 + 1);
        float bb[8] = {b0.x, b0.y, b0.z, b0.w, b1.x, b1.y, b1.z, b1.w};
        #pragma unroll
        for (int r = 0; r < 4; r++) {
            int pair = pg + 24*r;
            int prow = min(base + (pair >> 4), NP-1);
            const float4* qp = (const float4*)(g_X + (size_t)prow*192) + hg*2;
            float4 q0 = __ldg(qp), q1 = __ldg(qp + 1);
            float qf[8] = {q0.x, q0.y, q0.z, q0.w, q1.x, q1.y, q1.z, q1.w};
            int g = sm->Idx[pair];
            const float4* kp = (const float4*)(g_X + (size_t)g*192 + 64) + hg*2;
            const float4* vp = (const float4*)(g_X + (size_t)g*192 + 128) + hg*2;
            float4 k0 = __ldg(kp), k1 = __ldg(kp + 1);
            float4 v0 = __ldg(vp), v1 = __ldg(vp + 1);
            float kf[8] = {k0.x, k0.y, k0.z, k0.w, k1.x, k1.y, k1.z, k1.w};
            float vf[8] = {v0.x, v0.y, v0.z, v0.w, v1.x, v1.y, v1.z, v1.w};
            float yv[8], uv[8];
            #pragma unroll
            for (int c = 0; c < 8; c++) {
                float pe = acc[r][c] + bb[c];
                yv[c] = qf[c] - kf[c] + pe;
                uv[c] = vf[c] + pe;
            }
            float* yb = sm->Y + pair*PAD + hg*8;
            float* ub = sm->U + pair*PAD + hg*8;
            *(float4*)yb       = make_float4(yv[0], yv[1], yv[2], yv[3]);
            *(float4*)(yb + 4) = make_float4(yv[4], yv[5], yv[6], yv[7]);
            *(float4*)ub       = make_float4(uv[0], uv[1], uv[2], uv[3]);
            *(float4*)(ub + 4) = make_float4(uv[4], uv[5], uv[6], uv[7]);
        }
    }
    __syncthreads();   // all warps done reading W (Wp2) before overwrite
    load_W(sm, Wt1, tid);          // stage 2 weights
    __syncthreads();

    // ---- GEMM2: Y := relu(Y @ Wt1 + bt1) ----
    gemm4x8(sm->Y, sm->W, pg, hg, acc);
    __syncwarp();
    {
        float4 b0 = __ldg(((const float4*)bt1) + hg*2);
        float4 b1 = __ldg(((const float4*)bt1) + hg*2 + 1);
        float bb[8] = {b0.x, b0.y, b0.z, b0.w, b1.x, b1.y, b1.z, b1.w};
        #pragma unroll
        for (int r = 0; r < 4; r++) {
            float* yb = sm->Y + (pg + 24*r)*PAD + hg*8;
            float t[8];
            #pragma unroll
            for (int c = 0; c < 8; c++) t[c] = fmaxf(acc[r][c] + bb[c], 0.f);
            *(float4*)yb       = make_float4(t[0], t[1], t[2], t[3]);
            *(float4*)(yb + 4) = make_float4(t[4], t[5], t[6], t[7]);
        }
    }
    __syncthreads();   // all warps done reading W (Wt1) before overwrite
    load_W(sm, Wt2, tid);          // stage 3 weights
    __syncthreads();

    // ---- GEMM3: Y := (Y @ Wt2 + bt2) / 8 ----
    gemm4x8(sm->Y, sm->W, pg, hg, acc);
    __syncwarp();
    {
        float4 b0 = __ldg(((const float4*)bt2) + hg*2);
        float4 b1 = __ldg(((const float4*)bt2) + hg*2 + 1);
        float bb[8] = {b0.x, b0.y, b0.z, b0.w, b1.x, b1.y, b1.z, b1.w};
        #pragma unroll
        for (int r = 0; r < 4; r++) {
            float* yb = sm->Y + (pg + 24*r)*PAD + hg*8;
            float t[8];
            #pragma unroll
            for (int c = 0; c < 8; c++) t[c] = (acc[r][c] + bb[c]) * 0.125f;
            *(float4*)yb       = make_float4(t[0], t[1], t[2], t[3]);
            *(float4*)(yb + 4) = make_float4(t[4], t[5], t[6], t[7]);
        }
    }
    __syncthreads();   // cross-warp: softmax reads all 16 rows of each point

    // ---- softmax over j + weighted sum with VPE ----
    #pragma unroll
    for (int e = tid; e < PTS*64; e += 192) {
        int p = e >> 6, h = e & 63;
        float m = -finf();
        #pragma unroll
        for (int j = 0; j < 16; j++)
            m = fmaxf(m, sm->Y[(p*16 + j)*PAD + h]);
        float num = 0.f, den = 0.f;
        #pragma unroll
        for (int j = 0; j < 16; j++) {
            float ex = __expf(sm->Y[(p*16 + j)*PAD + h] - m);
            den += ex;
            num = fmaf(ex, sm->U[(p*16 + j)*PAD + h], num);
        }
        sm->Res[p*64 + h] = num / den;
    }
    __syncthreads();   // cross-warp: final GEMV reads full Res rows

    // ---- final: out = Res @ Wa + ba + features ----
    #pragma unroll
    for (int e = tid; e < PTS*64; e += 192) {
        int p = e >> 6, h = e & 63;
        int row = base + p;
        if (row < NP) {
            float a = 0.f;
            const float* wa = Wa + h;
            #pragma unroll 8
            for (int i = 0; i < 64; i++)
                a = fmaf(sm->Res[p*64 + i], __ldg(wa + i*64), a);
            out[(size_t)row*64 + h] = a + __ldg(ba + h) + __ldg(features + (size_t)row*64 + h);
        }
    }
}

// ================= launch =================
extern "C" void kernel_launch(void* const* d_in, const int* in_sizes, int n_in,
                              void* d_out, int out_size) {
    const float* xyzp     = (const float*)d_in[0];
    const float* features = (const float*)d_in[1];
    const float* Wk  = (const float*)d_in[2];
    const float* bk  = (const float*)d_in[3];
    const float* Wq  = (const float*)d_in[4];
    const float* Wks = (const float*)d_in[5];
    const float* Wv  = (const float*)d_in[6];
    const float* Wp1 = (const float*)d_in[7];
    const float* bp1 = (const float*)d_in[8];
    const float* Wp2 = (const float*)d_in[9];
    const float* bp2 = (const float*)d_in[10];
    const float* Wt1 = (const float*)d_in[11];
    const float* bt1 = (const float*)d_in[12];
    const float* Wt2 = (const float*)d_in[13];
    const float* bt2 = (const float*)d_in[14];
    const float* Wa  = (const float*)d_in[15];
    const float* ba  = (const float*)d_in[16];
    float* out = (float*)d_out;

    cudaFuncSetAttribute(transform_kernel, cudaFuncAttributeMaxDynamicSharedMemorySize,
                         (int)sizeof(SmemT));
    cudaFuncSetAttribute(attn_kernel, cudaFuncAttributeMaxDynamicSharedMemorySize,
                         (int)sizeof(SmemA));

    fold_kernel<<<16, 256>>>(Wk, bk, Wq, Wks, Wv);
    transform_kernel<<<NP/16, 192, sizeof(SmemT)>>>(features, xyzp, Wp1);
    knn_kernel<<<512, 128>>>();
    int attn_grid = (NP + PTS - 1) / PTS;
    attn_kernel<<<attn_grid, 192, sizeof(SmemA)>>>(features, bp1, Wp2, bp2,
                                                   Wt1, bt1, Wt2, bt2, Wa, ba, out);
}